// round 1
// baseline (speedup 1.0000x reference)
#include <cuda_runtime.h>
#include <math_constants.h>

// Problem constants
#define D_MODEL   1024
#define NUM_HEADS 16
#define HEAD_DIM  64
#define BATCH     4
#define SEQ       2048
#define M_TOTAL   (BATCH * SEQ)          // 8192 rows

// Scratch (allocation-free rule: __device__ globals)
__device__ float g_q[BATCH * NUM_HEADS * SEQ * HEAD_DIM];   // [B,H,S,Dh]
__device__ float g_k[BATCH * NUM_HEADS * SEQ * HEAD_DIM];
__device__ float g_v[BATCH * NUM_HEADS * SEQ * HEAD_DIM];
__device__ float g_o[M_TOTAL * D_MODEL];                    // [B*S, D] attention output

// ---------------------------------------------------------------------------
// NT SGEMM body: C = A @ W^T + bias
//   A: [M_TOTAL, 1024] row-major (K contiguous)
//   W: [1024, 1024] row-major (N x K, K contiguous)
// BM=BN=128, BK=8, 256 threads, 8x8 per thread.
// mode 0: store row-major C[m*1024+n]
// mode 1: store QKV layout dst[((b*16+h)*2048+s)*64+d],  m=b*2048+s, n=h*64+d
// ---------------------------------------------------------------------------
__device__ __forceinline__ void gemm_body(const float* __restrict__ A,
                                          const float* __restrict__ W,
                                          const float* __restrict__ bias,
                                          float* __restrict__ C,
                                          int mode)
{
    __shared__ float As[8][128];
    __shared__ float Bs[8][128];

    const int tid = threadIdx.x;
    const int bm  = blockIdx.y * 128;
    const int bn  = blockIdx.x * 128;
    const int tr  = tid >> 4;      // 0..15
    const int tc  = tid & 15;      // 0..15

    const int lrow = tid >> 1;           // 0..127
    const int lcol = (tid & 1) << 2;     // 0 or 4

    const float* Ap = A + (size_t)(bm + lrow) * D_MODEL + lcol;
    const float* Wp = W + (size_t)(bn + lrow) * D_MODEL + lcol;

    float acc[8][8];
    #pragma unroll
    for (int i = 0; i < 8; i++)
        #pragma unroll
        for (int j = 0; j < 8; j++) acc[i][j] = 0.f;

    for (int k0 = 0; k0 < D_MODEL; k0 += 8) {
        float4 a4 = *(const float4*)(Ap + k0);
        float4 b4 = *(const float4*)(Wp + k0);
        __syncthreads();   // previous iteration's compute done
        As[lcol + 0][lrow] = a4.x;
        As[lcol + 1][lrow] = a4.y;
        As[lcol + 2][lrow] = a4.z;
        As[lcol + 3][lrow] = a4.w;
        Bs[lcol + 0][lrow] = b4.x;
        Bs[lcol + 1][lrow] = b4.y;
        Bs[lcol + 2][lrow] = b4.z;
        Bs[lcol + 3][lrow] = b4.w;
        __syncthreads();

        #pragma unroll
        for (int k = 0; k < 8; k++) {
            float ra[8], rb[8];
            #pragma unroll
            for (int i = 0; i < 8; i++) ra[i] = As[k][tr * 8 + i];
            #pragma unroll
            for (int j = 0; j < 8; j++) rb[j] = Bs[k][tc * 8 + j];
            #pragma unroll
            for (int i = 0; i < 8; i++)
                #pragma unroll
                for (int j = 0; j < 8; j++)
                    acc[i][j] = fmaf(ra[i], rb[j], acc[i][j]);
        }
    }

    // epilogue: bias + store
    #pragma unroll
    for (int i = 0; i < 8; i++) {
        const int m = bm + tr * 8 + i;
        #pragma unroll
        for (int j = 0; j < 8; j += 4) {
            const int n = bn + tc * 8 + j;
            float4 r;
            r.x = acc[i][j + 0] + bias[n + 0];
            r.y = acc[i][j + 1] + bias[n + 1];
            r.z = acc[i][j + 2] + bias[n + 2];
            r.w = acc[i][j + 3] + bias[n + 3];
            if (mode == 0) {
                *(float4*)(C + (size_t)m * D_MODEL + n) = r;
            } else {
                const int b = m >> 11, s = m & 2047;
                const int h = n >> 6,  d = n & 63;
                *(float4*)(C + (((size_t)(b * NUM_HEADS + h) * SEQ + s) << 6) + d) = r;
            }
        }
    }
}

// Fused QKV projection: grid.z selects which of Q/K/V to compute.
__global__ __launch_bounds__(256)
void qkv_gemm_kernel(const float* __restrict__ x,
                     const float* __restrict__ Wq, const float* __restrict__ bq,
                     const float* __restrict__ Wk, const float* __restrict__ bk,
                     const float* __restrict__ Wv, const float* __restrict__ bv)
{
    const float* W; const float* b; float* dst;
    if (blockIdx.z == 0)      { W = Wq; b = bq; dst = g_q; }
    else if (blockIdx.z == 1) { W = Wk; b = bk; dst = g_k; }
    else                      { W = Wv; b = bv; dst = g_v; }
    gemm_body(x, W, b, dst, 1);
}

// Output projection: out = g_o @ Wo^T + bo
__global__ __launch_bounds__(256)
void out_gemm_kernel(const float* __restrict__ Wo, const float* __restrict__ bo,
                     float* __restrict__ out)
{
    gemm_body(g_o, Wo, bo, out, 0);
}

// ---------------------------------------------------------------------------
// Flash-style attention. One thread per query row; softmax thread-local.
// Block: 128 threads = 128 queries. Grid: (B*H, SEQ/128).
// K/V streamed in 64-key tiles through shared memory.
// ---------------------------------------------------------------------------
__global__ __launch_bounds__(128)
void attn_kernel()
{
    __shared__ float Ks[64][64];
    __shared__ float Vs[64][64];

    const int bh    = blockIdx.x;            // b*16 + h
    const int qbase = blockIdx.y * 128;
    const int t     = threadIdx.x;
    const int s_row = qbase + t;

    const float scale = 0.125f;              // 1/sqrt(64)

    // load this thread's q row (pre-scaled)
    float q[64];
    {
        const float4* Qp = (const float4*)(g_q + ((size_t)bh * SEQ + s_row) * 64);
        #pragma unroll
        for (int i = 0; i < 16; i++) {
            float4 v4 = Qp[i];
            q[4*i+0] = v4.x * scale;
            q[4*i+1] = v4.y * scale;
            q[4*i+2] = v4.z * scale;
            q[4*i+3] = v4.w * scale;
        }
    }

    float o[64];
    #pragma unroll
    for (int d = 0; d < 64; d++) o[d] = 0.f;
    float mrow = -3.0e38f;
    float lrow = 0.f;

    const float4* Kbase = (const float4*)(g_k + (size_t)bh * SEQ * 64);
    const float4* Vbase = (const float4*)(g_v + (size_t)bh * SEQ * 64);

    #pragma unroll 1
    for (int kt = 0; kt < SEQ; kt += 64) {
        __syncthreads();
        // cooperative load of 64x64 K and V tiles (contiguous 4096 floats each)
        {
            const float4* Kg = Kbase + kt * 16;   // kt*64/4
            const float4* Vg = Vbase + kt * 16;
            float4* Kd = (float4*)&Ks[0][0];
            float4* Vd = (float4*)&Vs[0][0];
            #pragma unroll
            for (int i = 0; i < 8; i++) {
                Kd[t + i * 128] = Kg[t + i * 128];
                Vd[t + i * 128] = Vg[t + i * 128];
            }
        }
        __syncthreads();

        // 4 chunks of 16 keys
        #pragma unroll 1
        for (int jc = 0; jc < 4; jc++) {
            float sc[16];
            #pragma unroll
            for (int j = 0; j < 16; j++) {
                const int jj = jc * 16 + j;
                const float4* Kr = (const float4*)Ks[jj];
                float acc = 0.f;
                #pragma unroll
                for (int d4 = 0; d4 < 16; d4++) {
                    float4 kv = Kr[d4];
                    acc = fmaf(q[4*d4+0], kv.x, acc);
                    acc = fmaf(q[4*d4+1], kv.y, acc);
                    acc = fmaf(q[4*d4+2], kv.z, acc);
                    acc = fmaf(q[4*d4+3], kv.w, acc);
                }
                sc[j] = acc;
            }
            float mnew = mrow;
            #pragma unroll
            for (int j = 0; j < 16; j++) mnew = fmaxf(mnew, sc[j]);
            const float corr = __expf(mrow - mnew);
            mrow = mnew;
            lrow *= corr;
            #pragma unroll
            for (int d = 0; d < 64; d++) o[d] *= corr;

            #pragma unroll
            for (int j = 0; j < 16; j++) {
                const int jj = jc * 16 + j;
                const float p = __expf(sc[j] - mrow);
                lrow += p;
                const float4* Vr = (const float4*)Vs[jj];
                #pragma unroll
                for (int d4 = 0; d4 < 16; d4++) {
                    float4 vv = Vr[d4];
                    o[4*d4+0] = fmaf(p, vv.x, o[4*d4+0]);
                    o[4*d4+1] = fmaf(p, vv.y, o[4*d4+1]);
                    o[4*d4+2] = fmaf(p, vv.z, o[4*d4+2]);
                    o[4*d4+3] = fmaf(p, vv.w, o[4*d4+3]);
                }
            }
        }
    }

    const float inv = 1.0f / lrow;
    const int b = bh >> 4, h = bh & 15;
    float4* Op = (float4*)(g_o + ((size_t)(b * SEQ + s_row)) * D_MODEL + h * 64);
    #pragma unroll
    for (int i = 0; i < 16; i++) {
        float4 r;
        r.x = o[4*i+0] * inv;
        r.y = o[4*i+1] * inv;
        r.z = o[4*i+2] * inv;
        r.w = o[4*i+3] * inv;
        Op[i] = r;
    }
}

// ---------------------------------------------------------------------------
extern "C" void kernel_launch(void* const* d_in, const int* in_sizes, int n_in,
                              void* d_out, int out_size)
{
    const float* x  = (const float*)d_in[0];
    const float* Wq = (const float*)d_in[1];
    const float* bq = (const float*)d_in[2];
    const float* Wk = (const float*)d_in[3];
    const float* bk = (const float*)d_in[4];
    const float* Wv = (const float*)d_in[5];
    const float* bv = (const float*)d_in[6];
    const float* Wo = (const float*)d_in[7];
    const float* bo = (const float*)d_in[8];
    float* out = (float*)d_out;

    // QKV projections (fused into one launch, z selects matrix)
    dim3 gqkv(D_MODEL / 128, M_TOTAL / 128, 3);
    qkv_gemm_kernel<<<gqkv, 256>>>(x, Wq, bq, Wk, bk, Wv, bv);

    // Attention
    dim3 gattn(BATCH * NUM_HEADS, SEQ / 128);
    attn_kernel<<<gattn, 128>>>();

    // Output projection
    dim3 gout(D_MODEL / 128, M_TOTAL / 128);
    out_gemm_kernel<<<gout, 256>>>(Wo, bo, out);
}

// round 3
// speedup vs baseline: 1.3239x; 1.3239x over previous
#include <cuda_runtime.h>
#include <cuda_bf16.h>
#include <cstdint>

// Problem constants
#define D_MODEL   1024
#define NUM_HEADS 16
#define HEAD_DIM  64
#define BATCH     4
#define SEQ       2048
#define M_TOTAL   (BATCH * SEQ)          // 8192 rows

// Scratch (allocation-free rule: __device__ globals)
__device__ float g_q[BATCH * NUM_HEADS * SEQ * HEAD_DIM];   // [B,H,S,Dh]
__device__ float g_k[BATCH * NUM_HEADS * SEQ * HEAD_DIM];
__device__ float g_v[BATCH * NUM_HEADS * SEQ * HEAD_DIM];
__device__ float g_o[M_TOTAL * D_MODEL];                    // [B*S, D]

// ===========================================================================
// mma.sync helpers (sm_80+ baseline PTX — works on plain sm_103 target)
// ===========================================================================
static __device__ __forceinline__ uint32_t smem_u32(const void* p) {
    uint32_t a;
    asm("{ .reg .u64 t; cvta.to.shared.u64 t, %1; cvt.u32.u64 %0, t; }"
        : "=r"(a) : "l"(p));
    return a;
}

static __device__ __forceinline__ void ldsm_x4(uint32_t (&r)[4], uint32_t addr) {
    asm volatile("ldmatrix.sync.aligned.m8n8.x4.shared.b16 {%0,%1,%2,%3}, [%4];"
                 : "=r"(r[0]), "=r"(r[1]), "=r"(r[2]), "=r"(r[3]) : "r"(addr));
}

static __device__ __forceinline__ void mma16816(float (&d)[4],
                                                const uint32_t (&a)[4],
                                                const uint32_t* b)
{
    asm volatile(
        "mma.sync.aligned.m16n8k16.row.col.f32.bf16.bf16.f32 "
        "{%0,%1,%2,%3}, {%4,%5,%6,%7}, {%8,%9}, {%0,%1,%2,%3};"
        : "+f"(d[0]), "+f"(d[1]), "+f"(d[2]), "+f"(d[3])
        : "r"(a[0]), "r"(a[1]), "r"(a[2]), "r"(a[3]), "r"(b[0]), "r"(b[1]));
}

static __device__ __forceinline__ uint32_t pack_bf16x2(float a, float b) {
    __nv_bfloat162 t = __floats2bfloat162_rn(a, b);   // .x -> low 16 bits
    return *reinterpret_cast<uint32_t*>(&t);
}

// ===========================================================================
// HMMA 3xBF16-split GEMM: C[M_TOTAL x 1024] = A @ W^T + bias
//   A: [M,1024] row-major; W: [1024,1024] row-major (N x K, K contiguous)
//   CTA tile 128x128, BK=32. 8 warps, each 64(M) x 32(N).
//   A = Ah + Al (bf16 split), same for W. C ≈ Ah·Bh + Ah·Bl + Al·Bh, fp32 acc.
// mode 0: row-major C;  mode 1: scatter to [B,H,S,Dh] QKV layout.
// ===========================================================================
#define BK      32
#define STRIDE  40                        // padded row stride (bf16 elems)
#define TILE_E  (128 * STRIDE)            // elems per smem tile

static __device__ __forceinline__ void gemm_tc_body(const float* __restrict__ A,
                                                    const float* __restrict__ W,
                                                    const float* __restrict__ bias,
                                                    float* __restrict__ C,
                                                    int mode)
{
    __shared__ __nv_bfloat16 sAh[TILE_E], sAl[TILE_E], sBh[TILE_E], sBl[TILE_E];

    const int tid  = threadIdx.x;
    const int wid  = tid >> 5;
    const int lane = tid & 31;
    const int bm = blockIdx.y * 128;
    const int bn = blockIdx.x * 128;

    const int warp_m = (wid & 1) * 64;    // 2 warps along M
    const int warp_n = (wid >> 1) * 32;   // 4 warps along N

    const uint32_t uAh = smem_u32(sAh);
    const uint32_t uAl = smem_u32(sAl);
    const uint32_t uBh = smem_u32(sBh);
    const uint32_t uBl = smem_u32(sBl);

    float acc[4][4][4];
    #pragma unroll
    for (int i = 0; i < 4; i++)
        #pragma unroll
        for (int j = 0; j < 4; j++)
            #pragma unroll
            for (int c = 0; c < 4; c++) acc[i][j][c] = 0.f;

    // gmem load indexing: 128 rows x 8 float4 per row, 256 threads x 4 each
    const int lrow[4] = { (tid + 0*256) >> 3, (tid + 1*256) >> 3,
                          (tid + 2*256) >> 3, (tid + 3*256) >> 3 };
    const int lc4 = tid & 7;

    float4 av[4], bv[4];
    #pragma unroll
    for (int i = 0; i < 4; i++) {
        av[i] = __ldg((const float4*)(A + (size_t)(bm + lrow[i]) * D_MODEL + lc4 * 4));
        bv[i] = __ldg((const float4*)(W + (size_t)(bn + lrow[i]) * D_MODEL + lc4 * 4));
    }

    for (int chunk = 0; chunk < D_MODEL / BK; chunk++) {
        __syncthreads();   // previous compute done reading smem

        // convert + store hi/lo bf16 tiles
        #pragma unroll
        for (int i = 0; i < 4; i++) {
            const int e = lrow[i] * STRIDE + lc4 * 4;
            {
                float4 v = av[i];
                __nv_bfloat16 h0 = __float2bfloat16(v.x), h1 = __float2bfloat16(v.y);
                __nv_bfloat16 h2 = __float2bfloat16(v.z), h3 = __float2bfloat16(v.w);
                uint2 hi, lo;
                hi.x = pack_bf16x2(v.x, v.y);  hi.y = pack_bf16x2(v.z, v.w);
                lo.x = pack_bf16x2(v.x - __bfloat162float(h0), v.y - __bfloat162float(h1));
                lo.y = pack_bf16x2(v.z - __bfloat162float(h2), v.w - __bfloat162float(h3));
                *(uint2*)(sAh + e) = hi;
                *(uint2*)(sAl + e) = lo;
            }
            {
                float4 v = bv[i];
                __nv_bfloat16 h0 = __float2bfloat16(v.x), h1 = __float2bfloat16(v.y);
                __nv_bfloat16 h2 = __float2bfloat16(v.z), h3 = __float2bfloat16(v.w);
                uint2 hi, lo;
                hi.x = pack_bf16x2(v.x, v.y);  hi.y = pack_bf16x2(v.z, v.w);
                lo.x = pack_bf16x2(v.x - __bfloat162float(h0), v.y - __bfloat162float(h1));
                lo.y = pack_bf16x2(v.z - __bfloat162float(h2), v.w - __bfloat162float(h3));
                *(uint2*)(sBh + e) = hi;
                *(uint2*)(sBl + e) = lo;
            }
        }
        __syncthreads();

        // prefetch next chunk (LDG overlaps with MMA below)
        if (chunk + 1 < D_MODEL / BK) {
            const int k0 = (chunk + 1) * BK;
            #pragma unroll
            for (int i = 0; i < 4; i++) {
                av[i] = __ldg((const float4*)(A + (size_t)(bm + lrow[i]) * D_MODEL + k0 + lc4 * 4));
                bv[i] = __ldg((const float4*)(W + (size_t)(bn + lrow[i]) * D_MODEL + k0 + lc4 * 4));
            }
        }

        // 2 k-steps of 16
        #pragma unroll
        for (int ks = 0; ks < 2; ks++) {
            // A fragments: 4 m-frags (16x16 each), hi and lo
            uint32_t ah[4][4], al[4][4];
            {
                const int row = ((lane >> 3) & 1) * 8 + (lane & 7);
                const int kk  = ks * 16 + ((lane >> 4) & 1) * 8;
                #pragma unroll
                for (int mf = 0; mf < 4; mf++) {
                    const uint32_t off =
                        (uint32_t)(((warp_m + mf * 16 + row) * STRIDE + kk) * 2);
                    ldsm_x4(ah[mf], uAh + off);
                    ldsm_x4(al[mf], uAl + off);
                }
            }
            // B fragments: 4 n-frags of 8 (loaded as 2 x4 covering 16 n each)
            uint32_t bh[2][4], bl[2][4];
            {
                const int row = ((lane >> 4) & 1) * 8 + (lane & 7);
                const int kk  = ks * 16 + ((lane >> 3) & 1) * 8;
                #pragma unroll
                for (int nb = 0; nb < 2; nb++) {
                    const uint32_t off =
                        (uint32_t)(((warp_n + nb * 16 + row) * STRIDE + kk) * 2);
                    ldsm_x4(bh[nb], uBh + off);
                    ldsm_x4(bl[nb], uBl + off);
                }
            }
            #pragma unroll
            for (int mf = 0; mf < 4; mf++)
                #pragma unroll
                for (int nf = 0; nf < 4; nf++) {
                    const int nb = nf >> 1, o = (nf & 1) * 2;
                    mma16816(acc[mf][nf], ah[mf], &bh[nb][o]);
                    mma16816(acc[mf][nf], ah[mf], &bl[nb][o]);
                    mma16816(acc[mf][nf], al[mf], &bh[nb][o]);
                }
        }
    }

    // Epilogue: bias + store. d-frag: rows l/4, l/4+8; cols 2*(l%4), +1.
    const int er = lane >> 2;
    const int ec = (lane & 3) * 2;
    #pragma unroll
    for (int mf = 0; mf < 4; mf++) {
        #pragma unroll
        for (int nf = 0; nf < 4; nf++) {
            const int n = bn + warp_n + nf * 8 + ec;
            const float b0 = __ldg(bias + n), b1 = __ldg(bias + n + 1);
            #pragma unroll
            for (int half = 0; half < 2; half++) {
                const int m = bm + warp_m + mf * 16 + er + half * 8;
                float2 r;
                r.x = acc[mf][nf][half * 2 + 0] + b0;
                r.y = acc[mf][nf][half * 2 + 1] + b1;
                if (mode == 0) {
                    *(float2*)(C + (size_t)m * D_MODEL + n) = r;
                } else {
                    const int bb = m >> 11, s = m & 2047;
                    const int h = n >> 6,  d = n & 63;
                    *(float2*)(C + (((size_t)(bb * NUM_HEADS + h) * SEQ + s) << 6) + d) = r;
                }
            }
        }
    }
}

__global__ __launch_bounds__(256)
void qkv_gemm_kernel(const float* __restrict__ x,
                     const float* __restrict__ Wq, const float* __restrict__ bq,
                     const float* __restrict__ Wk, const float* __restrict__ bk,
                     const float* __restrict__ Wv, const float* __restrict__ bv)
{
    const float* W; const float* b; float* dst;
    if (blockIdx.z == 0)      { W = Wq; b = bq; dst = g_q; }
    else if (blockIdx.z == 1) { W = Wk; b = bk; dst = g_k; }
    else                      { W = Wv; b = bv; dst = g_v; }
    gemm_tc_body(x, W, b, dst, 1);
}

__global__ __launch_bounds__(256)
void out_gemm_kernel(const float* __restrict__ Wo, const float* __restrict__ bo,
                     float* __restrict__ out)
{
    gemm_tc_body(g_o, Wo, bo, out, 0);
}

// ---------------------------------------------------------------------------
// Flash-style attention (FFMA). One thread per query row; softmax thread-local.
// ---------------------------------------------------------------------------
__global__ __launch_bounds__(128)
void attn_kernel()
{
    __shared__ float Ks[64][64];
    __shared__ float Vs[64][64];

    const int bh    = blockIdx.x;
    const int qbase = blockIdx.y * 128;
    const int t     = threadIdx.x;
    const int s_row = qbase + t;

    const float scale = 0.125f;

    float q[64];
    {
        const float4* Qp = (const float4*)(g_q + ((size_t)bh * SEQ + s_row) * 64);
        #pragma unroll
        for (int i = 0; i < 16; i++) {
            float4 v4 = Qp[i];
            q[4*i+0] = v4.x * scale;
            q[4*i+1] = v4.y * scale;
            q[4*i+2] = v4.z * scale;
            q[4*i+3] = v4.w * scale;
        }
    }

    float o[64];
    #pragma unroll
    for (int d = 0; d < 64; d++) o[d] = 0.f;
    float mrow = -3.0e38f;
    float lrow = 0.f;

    const float4* Kbase = (const float4*)(g_k + (size_t)bh * SEQ * 64);
    const float4* Vbase = (const float4*)(g_v + (size_t)bh * SEQ * 64);

    #pragma unroll 1
    for (int kt = 0; kt < SEQ; kt += 64) {
        __syncthreads();
        {
            const float4* Kg = Kbase + kt * 16;
            const float4* Vg = Vbase + kt * 16;
            float4* Kd = (float4*)&Ks[0][0];
            float4* Vd = (float4*)&Vs[0][0];
            #pragma unroll
            for (int i = 0; i < 8; i++) {
                Kd[t + i * 128] = Kg[t + i * 128];
                Vd[t + i * 128] = Vg[t + i * 128];
            }
        }
        __syncthreads();

        #pragma unroll 1
        for (int jc = 0; jc < 4; jc++) {
            float sc[16];
            #pragma unroll
            for (int j = 0; j < 16; j++) {
                const int jj = jc * 16 + j;
                const float4* Kr = (const float4*)Ks[jj];
                float acc = 0.f;
                #pragma unroll
                for (int d4 = 0; d4 < 16; d4++) {
                    float4 kv = Kr[d4];
                    acc = fmaf(q[4*d4+0], kv.x, acc);
                    acc = fmaf(q[4*d4+1], kv.y, acc);
                    acc = fmaf(q[4*d4+2], kv.z, acc);
                    acc = fmaf(q[4*d4+3], kv.w, acc);
                }
                sc[j] = acc;
            }
            float mnew = mrow;
            #pragma unroll
            for (int j = 0; j < 16; j++) mnew = fmaxf(mnew, sc[j]);
            const float corr = __expf(mrow - mnew);
            mrow = mnew;
            lrow *= corr;
            #pragma unroll
            for (int d = 0; d < 64; d++) o[d] *= corr;

            #pragma unroll
            for (int j = 0; j < 16; j++) {
                const int jj = jc * 16 + j;
                const float p = __expf(sc[j] - mrow);
                lrow += p;
                const float4* Vr = (const float4*)Vs[jj];
                #pragma unroll
                for (int d4 = 0; d4 < 16; d4++) {
                    float4 vv = Vr[d4];
                    o[4*d4+0] = fmaf(p, vv.x, o[4*d4+0]);
                    o[4*d4+1] = fmaf(p, vv.y, o[4*d4+1]);
                    o[4*d4+2] = fmaf(p, vv.z, o[4*d4+2]);
                    o[4*d4+3] = fmaf(p, vv.w, o[4*d4+3]);
                }
            }
        }
    }

    const float inv = 1.0f / lrow;
    const int b = bh >> 4, h = bh & 15;
    float4* Op = (float4*)(g_o + ((size_t)(b * SEQ + s_row)) * D_MODEL + h * 64);
    #pragma unroll
    for (int i = 0; i < 16; i++) {
        float4 r;
        r.x = o[4*i+0] * inv;
        r.y = o[4*i+1] * inv;
        r.z = o[4*i+2] * inv;
        r.w = o[4*i+3] * inv;
        Op[i] = r;
    }
}

// ---------------------------------------------------------------------------
extern "C" void kernel_launch(void* const* d_in, const int* in_sizes, int n_in,
                              void* d_out, int out_size)
{
    const float* x  = (const float*)d_in[0];
    const float* Wq = (const float*)d_in[1];
    const float* bq = (const float*)d_in[2];
    const float* Wk = (const float*)d_in[3];
    const float* bk = (const float*)d_in[4];
    const float* Wv = (const float*)d_in[5];
    const float* bv = (const float*)d_in[6];
    const float* Wo = (const float*)d_in[7];
    const float* bo = (const float*)d_in[8];
    float* out = (float*)d_out;

    dim3 gqkv(D_MODEL / 128, M_TOTAL / 128, 3);
    qkv_gemm_kernel<<<gqkv, 256>>>(x, Wq, bq, Wk, bk, Wv, bv);

    dim3 gattn(BATCH * NUM_HEADS, SEQ / 128);
    attn_kernel<<<gattn, 128>>>();

    dim3 gout(D_MODEL / 128, M_TOTAL / 128);
    out_gemm_kernel<<<gout, 256>>>(Wo, bo, out);
}

// round 5
// speedup vs baseline: 3.2728x; 2.4720x over previous
#include <cuda_runtime.h>
#include <cuda_bf16.h>
#include <cstdint>

// Problem constants
#define D_MODEL   1024
#define NUM_HEADS 16
#define HEAD_DIM  64
#define BATCH     4
#define SEQ       2048
#define M_TOTAL   (BATCH * SEQ)          // 8192 rows

// Scratch (allocation-free rule: __device__ globals)
__device__ float g_q[BATCH * NUM_HEADS * SEQ * HEAD_DIM];   // [B,H,S,Dh]
__device__ float g_k[BATCH * NUM_HEADS * SEQ * HEAD_DIM];
__device__ float g_v[BATCH * NUM_HEADS * SEQ * HEAD_DIM];
__device__ float g_o[M_TOTAL * D_MODEL];                    // [B*S, D]

// ===========================================================================
// mma.sync helpers (sm_80+ baseline PTX — works on plain sm_103 target)
// ===========================================================================
static __device__ __forceinline__ uint32_t smem_u32(const void* p) {
    uint32_t a;
    asm("{ .reg .u64 t; cvta.to.shared.u64 t, %1; cvt.u32.u64 %0, t; }"
        : "=r"(a) : "l"(p));
    return a;
}

static __device__ __forceinline__ void ldsm_x4(uint32_t (&r)[4], uint32_t addr) {
    asm volatile("ldmatrix.sync.aligned.m8n8.x4.shared.b16 {%0,%1,%2,%3}, [%4];"
                 : "=r"(r[0]), "=r"(r[1]), "=r"(r[2]), "=r"(r[3]) : "r"(addr));
}

static __device__ __forceinline__ void ldsm_x4_t(uint32_t (&r)[4], uint32_t addr) {
    asm volatile("ldmatrix.sync.aligned.m8n8.x4.trans.shared.b16 {%0,%1,%2,%3}, [%4];"
                 : "=r"(r[0]), "=r"(r[1]), "=r"(r[2]), "=r"(r[3]) : "r"(addr));
}

static __device__ __forceinline__ void mma16816(float (&d)[4],
                                                const uint32_t (&a)[4],
                                                const uint32_t* b)
{
    asm volatile(
        "mma.sync.aligned.m16n8k16.row.col.f32.bf16.bf16.f32 "
        "{%0,%1,%2,%3}, {%4,%5,%6,%7}, {%8,%9}, {%0,%1,%2,%3};"
        : "+f"(d[0]), "+f"(d[1]), "+f"(d[2]), "+f"(d[3])
        : "r"(a[0]), "r"(a[1]), "r"(a[2]), "r"(a[3]), "r"(b[0]), "r"(b[1]));
}

static __device__ __forceinline__ uint32_t pack_bf16x2(float a, float b) {
    __nv_bfloat162 t = __floats2bfloat162_rn(a, b);   // .x -> low 16 bits
    return *reinterpret_cast<uint32_t*>(&t);
}

static __device__ __forceinline__ void split_f4(float4 v, uint2& hi, uint2& lo) {
    __nv_bfloat16 h0 = __float2bfloat16(v.x), h1 = __float2bfloat16(v.y);
    __nv_bfloat16 h2 = __float2bfloat16(v.z), h3 = __float2bfloat16(v.w);
    hi.x = pack_bf16x2(v.x, v.y);
    hi.y = pack_bf16x2(v.z, v.w);
    lo.x = pack_bf16x2(v.x - __bfloat162float(h0), v.y - __bfloat162float(h1));
    lo.y = pack_bf16x2(v.z - __bfloat162float(h2), v.w - __bfloat162float(h3));
}

// ===========================================================================
// HMMA 3xBF16-split GEMM (unchanged from R3 — verified)
// ===========================================================================
#define BK      32
#define STRIDE  40
#define TILE_E  (128 * STRIDE)

static __device__ __forceinline__ void gemm_tc_body(const float* __restrict__ A,
                                                    const float* __restrict__ W,
                                                    const float* __restrict__ bias,
                                                    float* __restrict__ C,
                                                    int mode)
{
    __shared__ __nv_bfloat16 sAh[TILE_E], sAl[TILE_E], sBh[TILE_E], sBl[TILE_E];

    const int tid  = threadIdx.x;
    const int wid  = tid >> 5;
    const int lane = tid & 31;
    const int bm = blockIdx.y * 128;
    const int bn = blockIdx.x * 128;

    const int warp_m = (wid & 1) * 64;
    const int warp_n = (wid >> 1) * 32;

    const uint32_t uAh = smem_u32(sAh);
    const uint32_t uAl = smem_u32(sAl);
    const uint32_t uBh = smem_u32(sBh);
    const uint32_t uBl = smem_u32(sBl);

    float acc[4][4][4];
    #pragma unroll
    for (int i = 0; i < 4; i++)
        #pragma unroll
        for (int j = 0; j < 4; j++)
            #pragma unroll
            for (int c = 0; c < 4; c++) acc[i][j][c] = 0.f;

    const int lrow[4] = { (tid + 0*256) >> 3, (tid + 1*256) >> 3,
                          (tid + 2*256) >> 3, (tid + 3*256) >> 3 };
    const int lc4 = tid & 7;

    float4 av[4], bv[4];
    #pragma unroll
    for (int i = 0; i < 4; i++) {
        av[i] = __ldg((const float4*)(A + (size_t)(bm + lrow[i]) * D_MODEL + lc4 * 4));
        bv[i] = __ldg((const float4*)(W + (size_t)(bn + lrow[i]) * D_MODEL + lc4 * 4));
    }

    for (int chunk = 0; chunk < D_MODEL / BK; chunk++) {
        __syncthreads();

        #pragma unroll
        for (int i = 0; i < 4; i++) {
            const int e = lrow[i] * STRIDE + lc4 * 4;
            uint2 hi, lo;
            split_f4(av[i], hi, lo);
            *(uint2*)(sAh + e) = hi;
            *(uint2*)(sAl + e) = lo;
            split_f4(bv[i], hi, lo);
            *(uint2*)(sBh + e) = hi;
            *(uint2*)(sBl + e) = lo;
        }
        __syncthreads();

        if (chunk + 1 < D_MODEL / BK) {
            const int k0 = (chunk + 1) * BK;
            #pragma unroll
            for (int i = 0; i < 4; i++) {
                av[i] = __ldg((const float4*)(A + (size_t)(bm + lrow[i]) * D_MODEL + k0 + lc4 * 4));
                bv[i] = __ldg((const float4*)(W + (size_t)(bn + lrow[i]) * D_MODEL + k0 + lc4 * 4));
            }
        }

        #pragma unroll
        for (int ks = 0; ks < 2; ks++) {
            uint32_t ah[4][4], al[4][4];
            {
                const int row = ((lane >> 3) & 1) * 8 + (lane & 7);
                const int kk  = ks * 16 + ((lane >> 4) & 1) * 8;
                #pragma unroll
                for (int mf = 0; mf < 4; mf++) {
                    const uint32_t off =
                        (uint32_t)(((warp_m + mf * 16 + row) * STRIDE + kk) * 2);
                    ldsm_x4(ah[mf], uAh + off);
                    ldsm_x4(al[mf], uAl + off);
                }
            }
            uint32_t bh[2][4], bl[2][4];
            {
                const int row = ((lane >> 4) & 1) * 8 + (lane & 7);
                const int kk  = ks * 16 + ((lane >> 3) & 1) * 8;
                #pragma unroll
                for (int nb = 0; nb < 2; nb++) {
                    const uint32_t off =
                        (uint32_t)(((warp_n + nb * 16 + row) * STRIDE + kk) * 2);
                    ldsm_x4(bh[nb], uBh + off);
                    ldsm_x4(bl[nb], uBl + off);
                }
            }
            #pragma unroll
            for (int mf = 0; mf < 4; mf++)
                #pragma unroll
                for (int nf = 0; nf < 4; nf++) {
                    const int nb = nf >> 1, o = (nf & 1) * 2;
                    mma16816(acc[mf][nf], ah[mf], &bh[nb][o]);
                    mma16816(acc[mf][nf], ah[mf], &bl[nb][o]);
                    mma16816(acc[mf][nf], al[mf], &bh[nb][o]);
                }
        }
    }

    const int er = lane >> 2;
    const int ec = (lane & 3) * 2;
    #pragma unroll
    for (int mf = 0; mf < 4; mf++) {
        #pragma unroll
        for (int nf = 0; nf < 4; nf++) {
            const int n = bn + warp_n + nf * 8 + ec;
            const float b0 = __ldg(bias + n), b1 = __ldg(bias + n + 1);
            #pragma unroll
            for (int half = 0; half < 2; half++) {
                const int m = bm + warp_m + mf * 16 + er + half * 8;
                float2 r;
                r.x = acc[mf][nf][half * 2 + 0] + b0;
                r.y = acc[mf][nf][half * 2 + 1] + b1;
                if (mode == 0) {
                    *(float2*)(C + (size_t)m * D_MODEL + n) = r;
                } else {
                    const int bb = m >> 11, s = m & 2047;
                    const int h = n >> 6,  d = n & 63;
                    *(float2*)(C + (((size_t)(bb * NUM_HEADS + h) * SEQ + s) << 6) + d) = r;
                }
            }
        }
    }
}

__global__ __launch_bounds__(256)
void qkv_gemm_kernel(const float* __restrict__ x,
                     const float* __restrict__ Wq, const float* __restrict__ bq,
                     const float* __restrict__ Wk, const float* __restrict__ bk,
                     const float* __restrict__ Wv, const float* __restrict__ bv)
{
    const float* W; const float* b; float* dst;
    if (blockIdx.z == 0)      { W = Wq; b = bq; dst = g_q; }
    else if (blockIdx.z == 1) { W = Wk; b = bk; dst = g_k; }
    else                      { W = Wv; b = bv; dst = g_v; }
    gemm_tc_body(x, W, b, dst, 1);
}

__global__ __launch_bounds__(256)
void out_gemm_kernel(const float* __restrict__ Wo, const float* __restrict__ bo,
                     float* __restrict__ out)
{
    gemm_tc_body(g_o, Wo, bo, out, 0);
}

// ===========================================================================
// Tensor-core flash attention with 3xBF16 split.
// CTA: 64 q-rows, 4 warps x 16 rows. K/V tiles of 64 keys.
//   S = Qh·Kh + Qh·Kl + Ql·Kh  (Q pre-scaled by 1/8)
//   O += Ph·Vh + Ph·Vl + Pl·Vh
// ===========================================================================
#define AT_STRIDE 72   // bf16 elems per smem row (64 + 8 pad)

__global__ __launch_bounds__(128)
void attn_kernel()
{
    __shared__ __nv_bfloat16 sKh[64 * AT_STRIDE], sKl[64 * AT_STRIDE];
    __shared__ __nv_bfloat16 sVh[64 * AT_STRIDE], sVl[64 * AT_STRIDE];

    const int bh    = blockIdx.x;            // b*16 + h
    const int qbase = blockIdx.y * 64;
    const int tid   = threadIdx.x;
    const int wid   = tid >> 5;
    const int lane  = tid & 31;
    const int warp_m = wid * 16;

    const uint32_t uKh = smem_u32(sKh);
    const uint32_t uKl = smem_u32(sKl);
    const uint32_t uVh = smem_u32(sVh);
    const uint32_t uVl = smem_u32(sVl);

    const float* Qg = g_q + ((size_t)bh * SEQ + qbase) * HEAD_DIM;
    const float* Kg = g_k + (size_t)bh * SEQ * HEAD_DIM;
    const float* Vg = g_v + (size_t)bh * SEQ * HEAD_DIM;

    // ---- stage Q (scaled, split) via sK buffers, build register A-fragments
    #pragma unroll
    for (int i = 0; i < 8; i++) {
        const int idx = tid + i * 128;           // 1024 float4 total
        const int row = idx >> 4, c4 = idx & 15;
        float4 v = __ldg((const float4*)(Qg + row * HEAD_DIM + c4 * 4));
        v.x *= 0.125f; v.y *= 0.125f; v.z *= 0.125f; v.w *= 0.125f;
        uint2 hi, lo;
        split_f4(v, hi, lo);
        *(uint2*)(sKh + row * AT_STRIDE + c4 * 4) = hi;
        *(uint2*)(sKl + row * AT_STRIDE + c4 * 4) = lo;
    }
    __syncthreads();

    uint32_t qh[4][4], ql[4][4];
    {
        const int row = warp_m + ((lane >> 3) & 1) * 8 + (lane & 7);
        #pragma unroll
        for (int ks = 0; ks < 4; ks++) {
            const int kk = ks * 16 + ((lane >> 4) & 1) * 8;
            const uint32_t off = (uint32_t)((row * AT_STRIDE + kk) * 2);
            ldsm_x4(qh[ks], uKh + off);
            ldsm_x4(ql[ks], uKl + off);
        }
    }

    float o[8][4];
    #pragma unroll
    for (int nf = 0; nf < 8; nf++)
        #pragma unroll
        for (int c = 0; c < 4; c++) o[nf][c] = 0.f;
    float m0 = -1e30f, m1 = -1e30f, l0 = 0.f, l1 = 0.f;

    for (int kt = 0; kt < SEQ / 64; kt++) {
        __syncthreads();      // everyone done reading smem

        // ---- load + split K and V 64x64 tiles
        #pragma unroll
        for (int i = 0; i < 8; i++) {
            const int idx = tid + i * 128;
            const int row = idx >> 4, c4 = idx & 15;
            const int e = row * AT_STRIDE + c4 * 4;
            uint2 hi, lo;
            float4 kv = __ldg((const float4*)(Kg + (kt * 64 + row) * HEAD_DIM + c4 * 4));
            split_f4(kv, hi, lo);
            *(uint2*)(sKh + e) = hi;
            *(uint2*)(sKl + e) = lo;
            float4 vv = __ldg((const float4*)(Vg + (kt * 64 + row) * HEAD_DIM + c4 * 4));
            split_f4(vv, hi, lo);
            *(uint2*)(sVh + e) = hi;
            *(uint2*)(sVl + e) = lo;
        }
        __syncthreads();

        // ---- S = Q K^T  (16 q-rows x 64 keys per warp)
        float s[8][4];
        #pragma unroll
        for (int nf = 0; nf < 8; nf++)
            #pragma unroll
            for (int c = 0; c < 4; c++) s[nf][c] = 0.f;

        #pragma unroll
        for (int ks = 0; ks < 4; ks++) {
            uint32_t kbh[4][4], kbl[4][4];
            const int row = ((lane >> 4) & 1) * 8 + (lane & 7);
            const int kk  = ks * 16 + ((lane >> 3) & 1) * 8;
            #pragma unroll
            for (int nb = 0; nb < 4; nb++) {
                const uint32_t off =
                    (uint32_t)(((nb * 16 + row) * AT_STRIDE + kk) * 2);
                ldsm_x4(kbh[nb], uKh + off);
                ldsm_x4(kbl[nb], uKl + off);
            }
            #pragma unroll
            for (int nf = 0; nf < 8; nf++) {
                const int nb = nf >> 1, oo = (nf & 1) * 2;
                mma16816(s[nf], qh[ks], &kbh[nb][oo]);
                mma16816(s[nf], qh[ks], &kbl[nb][oo]);
                mma16816(s[nf], ql[ks], &kbh[nb][oo]);
            }
        }

        // ---- online softmax
        float mn0 = m0, mn1 = m1;
        #pragma unroll
        for (int nf = 0; nf < 8; nf++) {
            mn0 = fmaxf(mn0, fmaxf(s[nf][0], s[nf][1]));
            mn1 = fmaxf(mn1, fmaxf(s[nf][2], s[nf][3]));
        }
        mn0 = fmaxf(mn0, __shfl_xor_sync(0xffffffffu, mn0, 1));
        mn0 = fmaxf(mn0, __shfl_xor_sync(0xffffffffu, mn0, 2));
        mn1 = fmaxf(mn1, __shfl_xor_sync(0xffffffffu, mn1, 1));
        mn1 = fmaxf(mn1, __shfl_xor_sync(0xffffffffu, mn1, 2));
        const float c0 = __expf(m0 - mn0);
        const float c1 = __expf(m1 - mn1);
        m0 = mn0; m1 = mn1;
        l0 *= c0;  l1 *= c1;
        #pragma unroll
        for (int nf = 0; nf < 8; nf++) {
            o[nf][0] *= c0; o[nf][1] *= c0;
            o[nf][2] *= c1; o[nf][3] *= c1;
        }

        // ---- P = exp(S - m), split hi/lo, pack into A-fragments
        uint32_t pah[4][4], pal[4][4];
        #pragma unroll
        for (int nf = 0; nf < 8; nf++) {
            const float p0 = __expf(s[nf][0] - m0);
            const float p1 = __expf(s[nf][1] - m0);
            const float p2 = __expf(s[nf][2] - m1);
            const float p3 = __expf(s[nf][3] - m1);
            l0 += p0 + p1;
            l1 += p2 + p3;
            __nv_bfloat16 h0 = __float2bfloat16(p0), h1 = __float2bfloat16(p1);
            __nv_bfloat16 h2 = __float2bfloat16(p2), h3 = __float2bfloat16(p3);
            const int ks = nf >> 1, base = (nf & 1) * 2;
            pah[ks][base + 0] = pack_bf16x2(p0, p1);
            pah[ks][base + 1] = pack_bf16x2(p2, p3);
            pal[ks][base + 0] = pack_bf16x2(p0 - __bfloat162float(h0),
                                            p1 - __bfloat162float(h1));
            pal[ks][base + 1] = pack_bf16x2(p2 - __bfloat162float(h2),
                                            p3 - __bfloat162float(h3));
        }

        // ---- O += P V  (V^T fragments via ldmatrix.trans; dh split 0-31 / 32-63)
        #pragma unroll
        for (int ks = 0; ks < 4; ks++) {
            const int krow = ks * 16 + ((lane >> 3) & 1) * 8 + (lane & 7);
            #pragma unroll
            for (int half = 0; half < 2; half++) {
                uint32_t vbh[2][4], vbl[2][4];
                #pragma unroll
                for (int nb = 0; nb < 2; nb++) {
                    const int dh = half * 32 + nb * 16 + ((lane >> 4) & 1) * 8;
                    const uint32_t off = (uint32_t)((krow * AT_STRIDE + dh) * 2);
                    ldsm_x4_t(vbh[nb], uVh + off);
                    ldsm_x4_t(vbl[nb], uVl + off);
                }
                #pragma unroll
                for (int nf = 0; nf < 4; nf++) {
                    const int nb = nf >> 1, oo = (nf & 1) * 2;
                    mma16816(o[half * 4 + nf], pah[ks], &vbh[nb][oo]);
                    mma16816(o[half * 4 + nf], pah[ks], &vbl[nb][oo]);
                    mma16816(o[half * 4 + nf], pal[ks], &vbh[nb][oo]);
                }
            }
        }
    }

    // ---- finalize: reduce l over quad, normalize, store
    l0 += __shfl_xor_sync(0xffffffffu, l0, 1);
    l0 += __shfl_xor_sync(0xffffffffu, l0, 2);
    l1 += __shfl_xor_sync(0xffffffffu, l1, 1);
    l1 += __shfl_xor_sync(0xffffffffu, l1, 2);
    const float inv0 = 1.0f / l0, inv1 = 1.0f / l1;

    const int b = bh >> 4, h = bh & 15;
    const int row0 = qbase + warp_m + (lane >> 2);
    const int ec = (lane & 3) * 2;
    #pragma unroll
    for (int nf = 0; nf < 8; nf++) {
        const int dh = nf * 8 + ec;
        float2 r0, r1;
        r0.x = o[nf][0] * inv0;  r0.y = o[nf][1] * inv0;
        r1.x = o[nf][2] * inv1;  r1.y = o[nf][3] * inv1;
        *(float2*)(g_o + (size_t)(b * SEQ + row0) * D_MODEL + h * 64 + dh) = r0;
        *(float2*)(g_o + (size_t)(b * SEQ + row0 + 8) * D_MODEL + h * 64 + dh) = r1;
    }
}

// ---------------------------------------------------------------------------
extern "C" void kernel_launch(void* const* d_in, const int* in_sizes, int n_in,
                              void* d_out, int out_size)
{
    const float* x  = (const float*)d_in[0];
    const float* Wq = (const float*)d_in[1];
    const float* bq = (const float*)d_in[2];
    const float* Wk = (const float*)d_in[3];
    const float* bk = (const float*)d_in[4];
    const float* Wv = (const float*)d_in[5];
    const float* bv = (const float*)d_in[6];
    const float* Wo = (const float*)d_in[7];
    const float* bo = (const float*)d_in[8];
    float* out = (float*)d_out;

    dim3 gqkv(D_MODEL / 128, M_TOTAL / 128, 3);
    qkv_gemm_kernel<<<gqkv, 256>>>(x, Wq, bq, Wk, bk, Wv, bv);

    dim3 gattn(BATCH * NUM_HEADS, SEQ / 64);
    attn_kernel<<<gattn, 128>>>();

    dim3 gout(D_MODEL / 128, M_TOTAL / 128);
    out_gemm_kernel<<<gout, 256>>>(Wo, bo, out);
}

// round 6
// speedup vs baseline: 3.6146x; 1.1044x over previous
#include <cuda_runtime.h>
#include <cuda_bf16.h>
#include <cstdint>

// Problem constants
#define D_MODEL   1024
#define NUM_HEADS 16
#define HEAD_DIM  64
#define BATCH     4
#define SEQ       2048
#define M_TOTAL   (BATCH * SEQ)          // 8192 rows
#define QKV_E     (BATCH * NUM_HEADS * SEQ * HEAD_DIM)

// Pre-split bf16 scratch (allocation-free rule: __device__ globals)
__device__ __nv_bfloat16 g_xh[M_TOTAL * D_MODEL],  g_xl[M_TOTAL * D_MODEL];
__device__ __nv_bfloat16 g_wqh[D_MODEL * D_MODEL], g_wql[D_MODEL * D_MODEL];
__device__ __nv_bfloat16 g_wkh[D_MODEL * D_MODEL], g_wkl[D_MODEL * D_MODEL];
__device__ __nv_bfloat16 g_wvh[D_MODEL * D_MODEL], g_wvl[D_MODEL * D_MODEL];
__device__ __nv_bfloat16 g_woh[D_MODEL * D_MODEL], g_wol[D_MODEL * D_MODEL];
__device__ __nv_bfloat16 g_qh[QKV_E], g_ql[QKV_E];      // [B,H,S,Dh], Q pre-scaled
__device__ __nv_bfloat16 g_kh[QKV_E], g_kl[QKV_E];
__device__ __nv_bfloat16 g_vh[QKV_E], g_vl[QKV_E];
__device__ __nv_bfloat16 g_oh[M_TOTAL * D_MODEL], g_ol[M_TOTAL * D_MODEL];

// ===========================================================================
// helpers
// ===========================================================================
static __device__ __forceinline__ uint32_t smem_u32(const void* p) {
    uint32_t a;
    asm("{ .reg .u64 t; cvta.to.shared.u64 t, %1; cvt.u32.u64 %0, t; }"
        : "=r"(a) : "l"(p));
    return a;
}

static __device__ __forceinline__ void ldsm_x4(uint32_t (&r)[4], uint32_t addr) {
    asm volatile("ldmatrix.sync.aligned.m8n8.x4.shared.b16 {%0,%1,%2,%3}, [%4];"
                 : "=r"(r[0]), "=r"(r[1]), "=r"(r[2]), "=r"(r[3]) : "r"(addr));
}

static __device__ __forceinline__ void ldsm_x4_t(uint32_t (&r)[4], uint32_t addr) {
    asm volatile("ldmatrix.sync.aligned.m8n8.x4.trans.shared.b16 {%0,%1,%2,%3}, [%4];"
                 : "=r"(r[0]), "=r"(r[1]), "=r"(r[2]), "=r"(r[3]) : "r"(addr));
}

static __device__ __forceinline__ void mma16816(float (&d)[4],
                                                const uint32_t (&a)[4],
                                                const uint32_t* b)
{
    asm volatile(
        "mma.sync.aligned.m16n8k16.row.col.f32.bf16.bf16.f32 "
        "{%0,%1,%2,%3}, {%4,%5,%6,%7}, {%8,%9}, {%0,%1,%2,%3};"
        : "+f"(d[0]), "+f"(d[1]), "+f"(d[2]), "+f"(d[3])
        : "r"(a[0]), "r"(a[1]), "r"(a[2]), "r"(a[3]), "r"(b[0]), "r"(b[1]));
}

#define CP16(dst, src) \
    asm volatile("cp.async.cg.shared.global [%0], [%1], 16;" \
                 :: "r"(dst), "l"(src) : "memory")
#define CP_COMMIT() asm volatile("cp.async.commit_group;" ::: "memory")
#define CP_WAIT0()  asm volatile("cp.async.wait_group 0;" ::: "memory")
#define CP_WAIT1()  asm volatile("cp.async.wait_group 1;" ::: "memory")

static __device__ __forceinline__ uint32_t pack_bf16x2(float a, float b) {
    __nv_bfloat162 t = __floats2bfloat162_rn(a, b);
    return *reinterpret_cast<uint32_t*>(&t);
}

static __device__ __forceinline__ void split2_store(__nv_bfloat16* H, __nv_bfloat16* L,
                                                    size_t idx, float v0, float v1)
{
    __nv_bfloat16 h0 = __float2bfloat16(v0), h1 = __float2bfloat16(v1);
    *(uint32_t*)(H + idx) = pack_bf16x2(v0, v1);
    *(uint32_t*)(L + idx) = pack_bf16x2(v0 - __bfloat162float(h0),
                                        v1 - __bfloat162float(h1));
}

// ===========================================================================
// split pass: fp32 -> hi/lo bf16
// ===========================================================================
__global__ __launch_bounds__(256)
void split_kernel(const float* __restrict__ src, __nv_bfloat16* __restrict__ H,
                  __nv_bfloat16* __restrict__ L, int n4)
{
    for (int i = blockIdx.x * blockDim.x + threadIdx.x; i < n4;
         i += gridDim.x * blockDim.x) {
        float4 v = __ldg((const float4*)src + i);
        split2_store(H, L, (size_t)i * 4 + 0, v.x, v.y);
        split2_store(H, L, (size_t)i * 4 + 2, v.z, v.w);
    }
}

// ===========================================================================
// GEMM: C = (Ah+Al) @ (Bh+Bl)^T + bias   (3-term bf16 split, HMMA)
// A: [M,1024] bf16 hi/lo. B(W): [1024,1024] row-major (N x K) hi/lo.
// CTA 128x128, BK=32, double-buffered cp.async staging.
// mode 0: fp32 out [M,1024].  mode 1: split QKV out [B,H,S,Dh], val*scale.
// ===========================================================================
#define STRIDE  40                        // padded smem row (bf16 elems), 80B
#define TILE_E  (128 * STRIDE)            // 5120 elems per tile
#define STAGE_E (4 * TILE_E)              // Ah,Al,Bh,Bl
#define GEMM_SMEM_B (2 * STAGE_E * 2)     // bytes = 81920

extern __shared__ __nv_bfloat16 dsm[];

static __device__ __forceinline__ void gemm_issue(const __nv_bfloat16* Ah,
                                                  const __nv_bfloat16* Al,
                                                  const __nv_bfloat16* Bh,
                                                  const __nv_bfloat16* Bl,
                                                  uint32_t sb, int stage,
                                                  int bm, int bn, int k0, int tid)
{
    const uint32_t base = sb + (uint32_t)(stage * STAGE_E) * 2;
    #pragma unroll
    for (int i = 0; i < 2; i++) {
        const int idx = tid + i * 256;          // 0..511
        const int row = idx >> 2, c = idx & 3;  // row 0..127, 16B chunk 0..3
        const size_t gofs = (size_t)row * D_MODEL + k0 + c * 8;
        const uint32_t sofs = (uint32_t)(row * STRIDE + c * 8) * 2;
        CP16(base + 0 * TILE_E * 2 + sofs, Ah + (size_t)bm * D_MODEL + gofs);
        CP16(base + 1 * TILE_E * 2 + sofs, Al + (size_t)bm * D_MODEL + gofs);
        CP16(base + 2 * TILE_E * 2 + sofs, Bh + (size_t)bn * D_MODEL + gofs);
        CP16(base + 3 * TILE_E * 2 + sofs, Bl + (size_t)bn * D_MODEL + gofs);
    }
}

static __device__ __forceinline__ void gemm_tc_body(const __nv_bfloat16* __restrict__ Ah,
                                                    const __nv_bfloat16* __restrict__ Al,
                                                    const __nv_bfloat16* __restrict__ Bh,
                                                    const __nv_bfloat16* __restrict__ Bl,
                                                    const float* __restrict__ bias,
                                                    float* __restrict__ Cf,
                                                    __nv_bfloat16* __restrict__ Ch,
                                                    __nv_bfloat16* __restrict__ Cl,
                                                    int mode, float scale)
{
    const uint32_t sb = smem_u32(dsm);
    const int tid  = threadIdx.x;
    const int wid  = tid >> 5;
    const int lane = tid & 31;
    const int bm = blockIdx.y * 128;
    const int bn = blockIdx.x * 128;
    const int warp_m = (wid & 1) * 64;
    const int warp_n = (wid >> 1) * 32;

    float acc[4][4][4];
    #pragma unroll
    for (int i = 0; i < 4; i++)
        #pragma unroll
        for (int j = 0; j < 4; j++)
            #pragma unroll
            for (int c = 0; c < 4; c++) acc[i][j][c] = 0.f;

    gemm_issue(Ah, Al, Bh, Bl, sb, 0, bm, bn, 0, tid);
    CP_COMMIT();

    #pragma unroll 1
    for (int chunk = 0; chunk < D_MODEL / 32; chunk++) {
        const int cur = chunk & 1;
        if (chunk + 1 < D_MODEL / 32) {
            gemm_issue(Ah, Al, Bh, Bl, sb, cur ^ 1, bm, bn, (chunk + 1) * 32, tid);
            CP_COMMIT();
            CP_WAIT1();
        } else {
            CP_WAIT0();
        }
        __syncthreads();

        const uint32_t uAh = sb + (uint32_t)(cur * STAGE_E + 0 * TILE_E) * 2;
        const uint32_t uAl = sb + (uint32_t)(cur * STAGE_E + 1 * TILE_E) * 2;
        const uint32_t uBh = sb + (uint32_t)(cur * STAGE_E + 2 * TILE_E) * 2;
        const uint32_t uBl = sb + (uint32_t)(cur * STAGE_E + 3 * TILE_E) * 2;

        #pragma unroll
        for (int ks = 0; ks < 2; ks++) {
            uint32_t ah[4][4], al[4][4];
            {
                const int row = ((lane >> 3) & 1) * 8 + (lane & 7);
                const int kk  = ks * 16 + ((lane >> 4) & 1) * 8;
                #pragma unroll
                for (int mf = 0; mf < 4; mf++) {
                    const uint32_t off =
                        (uint32_t)(((warp_m + mf * 16 + row) * STRIDE + kk) * 2);
                    ldsm_x4(ah[mf], uAh + off);
                    ldsm_x4(al[mf], uAl + off);
                }
            }
            uint32_t bh[2][4], bl[2][4];
            {
                const int row = ((lane >> 4) & 1) * 8 + (lane & 7);
                const int kk  = ks * 16 + ((lane >> 3) & 1) * 8;
                #pragma unroll
                for (int nb = 0; nb < 2; nb++) {
                    const uint32_t off =
                        (uint32_t)(((warp_n + nb * 16 + row) * STRIDE + kk) * 2);
                    ldsm_x4(bh[nb], uBh + off);
                    ldsm_x4(bl[nb], uBl + off);
                }
            }
            #pragma unroll
            for (int mf = 0; mf < 4; mf++)
                #pragma unroll
                for (int nf = 0; nf < 4; nf++) {
                    const int nb = nf >> 1, o = (nf & 1) * 2;
                    mma16816(acc[mf][nf], ah[mf], &bh[nb][o]);
                    mma16816(acc[mf][nf], ah[mf], &bl[nb][o]);
                    mma16816(acc[mf][nf], al[mf], &bh[nb][o]);
                }
        }
        __syncthreads();
    }

    const int er = lane >> 2;
    const int ec = (lane & 3) * 2;
    #pragma unroll
    for (int mf = 0; mf < 4; mf++) {
        #pragma unroll
        for (int nf = 0; nf < 4; nf++) {
            const int n = bn + warp_n + nf * 8 + ec;
            const float b0 = __ldg(bias + n), b1 = __ldg(bias + n + 1);
            #pragma unroll
            for (int half = 0; half < 2; half++) {
                const int m = bm + warp_m + mf * 16 + er + half * 8;
                const float v0 = (acc[mf][nf][half * 2 + 0] + b0) * scale;
                const float v1 = (acc[mf][nf][half * 2 + 1] + b1) * scale;
                if (mode == 0) {
                    float2 r; r.x = v0; r.y = v1;
                    *(float2*)(Cf + (size_t)m * D_MODEL + n) = r;
                } else {
                    const int bb = m >> 11, s = m & 2047;
                    const int h = n >> 6,  d = n & 63;
                    const size_t idx =
                        (((size_t)(bb * NUM_HEADS + h) * SEQ + s) << 6) + d;
                    split2_store(Ch, Cl, idx, v0, v1);
                }
            }
        }
    }
}

__global__ __launch_bounds__(256)
void qkv_gemm_kernel(const float* __restrict__ bq, const float* __restrict__ bk,
                     const float* __restrict__ bv)
{
    if (blockIdx.z == 0)
        gemm_tc_body(g_xh, g_xl, g_wqh, g_wql, bq, nullptr, g_qh, g_ql, 1, 0.125f);
    else if (blockIdx.z == 1)
        gemm_tc_body(g_xh, g_xl, g_wkh, g_wkl, bk, nullptr, g_kh, g_kl, 1, 1.0f);
    else
        gemm_tc_body(g_xh, g_xl, g_wvh, g_wvl, bv, nullptr, g_vh, g_vl, 1, 1.0f);
}

__global__ __launch_bounds__(256)
void out_gemm_kernel(const float* __restrict__ bo, float* __restrict__ out)
{
    gemm_tc_body(g_oh, g_ol, g_woh, g_wol, bo, out, nullptr, nullptr, 0, 1.0f);
}

// ===========================================================================
// Tensor-core flash attention, pre-split inputs, cp.async double-buffered.
// CTA: 64 q-rows, 4 warps. K/V tiles of 64 keys.
// ===========================================================================
#define AT_STRIDE 72                       // bf16 elems per row (144B, 16B mult)
#define AT_TILE   (64 * AT_STRIDE)         // 4608 elems
#define AT_STAGE  (4 * AT_TILE)            // Kh,Kl,Vh,Vl
#define ATTN_SMEM_B (2 * AT_STAGE * 2)     // 73728 bytes

static __device__ __forceinline__ void attn_issue(uint32_t sb, int stage,
                                                  size_t kvbase, int kt, int tid)
{
    const uint32_t base = sb + (uint32_t)(stage * AT_STAGE) * 2;
    const __nv_bfloat16* srcs[4] = { g_kh, g_kl, g_vh, g_vl };
    #pragma unroll
    for (int i = 0; i < 16; i++) {
        const int idx = tid + i * 128;             // 0..2047
        const int arr = idx >> 9;                  // 0..3
        const int j   = idx & 511;
        const int row = j >> 3, c = j & 7;
        const __nv_bfloat16* src =
            srcs[arr] + kvbase + (size_t)(kt * 64 + row) * HEAD_DIM + c * 8;
        const uint32_t dst =
            base + (uint32_t)(arr * AT_TILE + row * AT_STRIDE + c * 8) * 2;
        CP16(dst, src);
    }
}

__global__ __launch_bounds__(128)
void attn_kernel()
{
    const uint32_t sb = smem_u32(dsm);

    const int bh    = blockIdx.x;            // b*16 + h
    const int qbase = blockIdx.y * 64;
    const int tid   = threadIdx.x;
    const int wid   = tid >> 5;
    const int lane  = tid & 31;
    const int warp_m = wid * 16;

    const size_t kvbase = (size_t)bh * SEQ * HEAD_DIM;

    // ---- stage Q (already scaled+split) into stage-0 Kh/Kl area
    #pragma unroll
    for (int i = 0; i < 8; i++) {
        const int idx = tid + i * 128;           // 0..1023
        const int arr = idx >> 9;                // 0: hi, 1: lo
        const int j   = idx & 511;
        const int row = j >> 3, c = j & 7;
        const __nv_bfloat16* src =
            (arr == 0 ? g_qh : g_ql) + kvbase + (size_t)(qbase + row) * HEAD_DIM + c * 8;
        const uint32_t dst = sb + (uint32_t)(arr * AT_TILE + row * AT_STRIDE + c * 8) * 2;
        CP16(dst, src);
    }
    CP_COMMIT();
    CP_WAIT0();
    __syncthreads();

    uint32_t qh[4][4], ql[4][4];
    {
        const int row = warp_m + ((lane >> 3) & 1) * 8 + (lane & 7);
        #pragma unroll
        for (int ks = 0; ks < 4; ks++) {
            const int kk = ks * 16 + ((lane >> 4) & 1) * 8;
            const uint32_t off = (uint32_t)((row * AT_STRIDE + kk) * 2);
            ldsm_x4(qh[ks], sb + off);
            ldsm_x4(ql[ks], sb + (uint32_t)(AT_TILE * 2) + off);
        }
    }
    __syncthreads();

    float o[8][4];
    #pragma unroll
    for (int nf = 0; nf < 8; nf++)
        #pragma unroll
        for (int c = 0; c < 4; c++) o[nf][c] = 0.f;
    float m0 = -1e30f, m1 = -1e30f, l0 = 0.f, l1 = 0.f;

    attn_issue(sb, 0, kvbase, 0, tid);
    CP_COMMIT();

    #pragma unroll 1
    for (int kt = 0; kt < SEQ / 64; kt++) {
        const int cur = kt & 1;
        if (kt + 1 < SEQ / 64) {
            attn_issue(sb, cur ^ 1, kvbase, kt + 1, tid);
            CP_COMMIT();
            CP_WAIT1();
        } else {
            CP_WAIT0();
        }
        __syncthreads();

        const uint32_t uKh = sb + (uint32_t)(cur * AT_STAGE + 0 * AT_TILE) * 2;
        const uint32_t uKl = sb + (uint32_t)(cur * AT_STAGE + 1 * AT_TILE) * 2;
        const uint32_t uVh = sb + (uint32_t)(cur * AT_STAGE + 2 * AT_TILE) * 2;
        const uint32_t uVl = sb + (uint32_t)(cur * AT_STAGE + 3 * AT_TILE) * 2;

        // ---- S = Q K^T
        float s[8][4];
        #pragma unroll
        for (int nf = 0; nf < 8; nf++)
            #pragma unroll
            for (int c = 0; c < 4; c++) s[nf][c] = 0.f;

        #pragma unroll
        for (int ks = 0; ks < 4; ks++) {
            uint32_t kbh[4][4], kbl[4][4];
            const int row = ((lane >> 4) & 1) * 8 + (lane & 7);
            const int kk  = ks * 16 + ((lane >> 3) & 1) * 8;
            #pragma unroll
            for (int nb = 0; nb < 4; nb++) {
                const uint32_t off =
                    (uint32_t)(((nb * 16 + row) * AT_STRIDE + kk) * 2);
                ldsm_x4(kbh[nb], uKh + off);
                ldsm_x4(kbl[nb], uKl + off);
            }
            #pragma unroll
            for (int nf = 0; nf < 8; nf++) {
                const int nb = nf >> 1, oo = (nf & 1) * 2;
                mma16816(s[nf], qh[ks], &kbh[nb][oo]);
                mma16816(s[nf], qh[ks], &kbl[nb][oo]);
                mma16816(s[nf], ql[ks], &kbh[nb][oo]);
            }
        }

        // ---- online softmax
        float mn0 = m0, mn1 = m1;
        #pragma unroll
        for (int nf = 0; nf < 8; nf++) {
            mn0 = fmaxf(mn0, fmaxf(s[nf][0], s[nf][1]));
            mn1 = fmaxf(mn1, fmaxf(s[nf][2], s[nf][3]));
        }
        mn0 = fmaxf(mn0, __shfl_xor_sync(0xffffffffu, mn0, 1));
        mn0 = fmaxf(mn0, __shfl_xor_sync(0xffffffffu, mn0, 2));
        mn1 = fmaxf(mn1, __shfl_xor_sync(0xffffffffu, mn1, 1));
        mn1 = fmaxf(mn1, __shfl_xor_sync(0xffffffffu, mn1, 2));
        const float c0 = __expf(m0 - mn0);
        const float c1 = __expf(m1 - mn1);
        m0 = mn0; m1 = mn1;
        l0 *= c0;  l1 *= c1;
        #pragma unroll
        for (int nf = 0; nf < 8; nf++) {
            o[nf][0] *= c0; o[nf][1] *= c0;
            o[nf][2] *= c1; o[nf][3] *= c1;
        }

        // ---- P = exp(S - m), split into A-fragments
        uint32_t pah[4][4], pal[4][4];
        #pragma unroll
        for (int nf = 0; nf < 8; nf++) {
            const float p0 = __expf(s[nf][0] - m0);
            const float p1 = __expf(s[nf][1] - m0);
            const float p2 = __expf(s[nf][2] - m1);
            const float p3 = __expf(s[nf][3] - m1);
            l0 += p0 + p1;
            l1 += p2 + p3;
            __nv_bfloat16 h0 = __float2bfloat16(p0), h1 = __float2bfloat16(p1);
            __nv_bfloat16 h2 = __float2bfloat16(p2), h3 = __float2bfloat16(p3);
            const int ks = nf >> 1, base = (nf & 1) * 2;
            pah[ks][base + 0] = pack_bf16x2(p0, p1);
            pah[ks][base + 1] = pack_bf16x2(p2, p3);
            pal[ks][base + 0] = pack_bf16x2(p0 - __bfloat162float(h0),
                                            p1 - __bfloat162float(h1));
            pal[ks][base + 1] = pack_bf16x2(p2 - __bfloat162float(h2),
                                            p3 - __bfloat162float(h3));
        }

        // ---- O += P V
        #pragma unroll
        for (int ks = 0; ks < 4; ks++) {
            const int krow = ks * 16 + ((lane >> 3) & 1) * 8 + (lane & 7);
            #pragma unroll
            for (int half = 0; half < 2; half++) {
                uint32_t vbh[2][4], vbl[2][4];
                #pragma unroll
                for (int nb = 0; nb < 2; nb++) {
                    const int dh = half * 32 + nb * 16 + ((lane >> 4) & 1) * 8;
                    const uint32_t off = (uint32_t)((krow * AT_STRIDE + dh) * 2);
                    ldsm_x4_t(vbh[nb], uVh + off);
                    ldsm_x4_t(vbl[nb], uVl + off);
                }
                #pragma unroll
                for (int nf = 0; nf < 4; nf++) {
                    const int nb = nf >> 1, oo = (nf & 1) * 2;
                    mma16816(o[half * 4 + nf], pah[ks], &vbh[nb][oo]);
                    mma16816(o[half * 4 + nf], pah[ks], &vbl[nb][oo]);
                    mma16816(o[half * 4 + nf], pal[ks], &vbh[nb][oo]);
                }
            }
        }
        __syncthreads();
    }

    // ---- finalize
    l0 += __shfl_xor_sync(0xffffffffu, l0, 1);
    l0 += __shfl_xor_sync(0xffffffffu, l0, 2);
    l1 += __shfl_xor_sync(0xffffffffu, l1, 1);
    l1 += __shfl_xor_sync(0xffffffffu, l1, 2);
    const float inv0 = 1.0f / l0, inv1 = 1.0f / l1;

    const int b = bh >> 4, h = bh & 15;
    const int row0 = qbase + warp_m + (lane >> 2);
    const int ec = (lane & 3) * 2;
    #pragma unroll
    for (int nf = 0; nf < 8; nf++) {
        const int dh = nf * 8 + ec;
        split2_store(g_oh, g_ol,
                     (size_t)(b * SEQ + row0) * D_MODEL + h * 64 + dh,
                     o[nf][0] * inv0, o[nf][1] * inv0);
        split2_store(g_oh, g_ol,
                     (size_t)(b * SEQ + row0 + 8) * D_MODEL + h * 64 + dh,
                     o[nf][2] * inv1, o[nf][3] * inv1);
    }
}

// ---------------------------------------------------------------------------
extern "C" void kernel_launch(void* const* d_in, const int* in_sizes, int n_in,
                              void* d_out, int out_size)
{
    const float* x  = (const float*)d_in[0];
    const float* Wq = (const float*)d_in[1];
    const float* bq = (const float*)d_in[2];
    const float* Wk = (const float*)d_in[3];
    const float* bk = (const float*)d_in[4];
    const float* Wv = (const float*)d_in[5];
    const float* bv = (const float*)d_in[6];
    const float* Wo = (const float*)d_in[7];
    const float* bo = (const float*)d_in[8];
    float* out = (float*)d_out;

    static int attr_done = 0;
    if (!attr_done) {
        cudaFuncSetAttribute(qkv_gemm_kernel,
                             cudaFuncAttributeMaxDynamicSharedMemorySize, GEMM_SMEM_B);
        cudaFuncSetAttribute(out_gemm_kernel,
                             cudaFuncAttributeMaxDynamicSharedMemorySize, GEMM_SMEM_B);
        cudaFuncSetAttribute(attn_kernel,
                             cudaFuncAttributeMaxDynamicSharedMemorySize, ATTN_SMEM_B);
        attr_done = 1;
    }

    // device-global pointers (host side)
    __nv_bfloat16 *xh, *xl, *wqh, *wql, *wkh, *wkl, *wvh, *wvl, *woh, *wol;
    cudaGetSymbolAddress((void**)&xh,  g_xh);  cudaGetSymbolAddress((void**)&xl,  g_xl);
    cudaGetSymbolAddress((void**)&wqh, g_wqh); cudaGetSymbolAddress((void**)&wql, g_wql);
    cudaGetSymbolAddress((void**)&wkh, g_wkh); cudaGetSymbolAddress((void**)&wkl, g_wkl);
    cudaGetSymbolAddress((void**)&wvh, g_wvh); cudaGetSymbolAddress((void**)&wvl, g_wvl);
    cudaGetSymbolAddress((void**)&woh, g_woh); cudaGetSymbolAddress((void**)&wol, g_wol);

    // split passes
    split_kernel<<<1024, 256>>>(x,  xh,  xl,  M_TOTAL * D_MODEL / 4);
    split_kernel<<<256,  256>>>(Wq, wqh, wql, D_MODEL * D_MODEL / 4);
    split_kernel<<<256,  256>>>(Wk, wkh, wkl, D_MODEL * D_MODEL / 4);
    split_kernel<<<256,  256>>>(Wv, wvh, wvl, D_MODEL * D_MODEL / 4);
    split_kernel<<<256,  256>>>(Wo, woh, wol, D_MODEL * D_MODEL / 4);

    // QKV projections
    dim3 gqkv(D_MODEL / 128, M_TOTAL / 128, 3);
    qkv_gemm_kernel<<<gqkv, 256, GEMM_SMEM_B>>>(bq, bk, bv);

    // Attention
    dim3 gattn(BATCH * NUM_HEADS, SEQ / 64);
    attn_kernel<<<gattn, 128, ATTN_SMEM_B>>>();

    // Output projection
    dim3 gout(D_MODEL / 128, M_TOTAL / 128);
    out_gemm_kernel<<<gout, 256, GEMM_SMEM_B>>>(bo, out);
}

// round 7
// speedup vs baseline: 3.6159x; 1.0004x over previous
#include <cuda_runtime.h>
#include <cuda_bf16.h>
#include <cstdint>

// Problem constants
#define D_MODEL   1024
#define NUM_HEADS 16
#define HEAD_DIM  64
#define BATCH     4
#define SEQ       2048
#define M_TOTAL   (BATCH * SEQ)          // 8192 rows
#define QKV_E     (BATCH * NUM_HEADS * SEQ * HEAD_DIM)

// Pre-split bf16 scratch (allocation-free rule: __device__ globals)
__device__ __nv_bfloat16 g_xh[M_TOTAL * D_MODEL],  g_xl[M_TOTAL * D_MODEL];
__device__ __nv_bfloat16 g_wqh[D_MODEL * D_MODEL], g_wql[D_MODEL * D_MODEL];
__device__ __nv_bfloat16 g_wkh[D_MODEL * D_MODEL], g_wkl[D_MODEL * D_MODEL];
__device__ __nv_bfloat16 g_wvh[D_MODEL * D_MODEL], g_wvl[D_MODEL * D_MODEL];
__device__ __nv_bfloat16 g_woh[D_MODEL * D_MODEL], g_wol[D_MODEL * D_MODEL];
__device__ __nv_bfloat16 g_qh[QKV_E], g_ql[QKV_E];      // [B,H,S,Dh], Q pre-scaled
__device__ __nv_bfloat16 g_kh[QKV_E], g_kl[QKV_E];
__device__ __nv_bfloat16 g_vh[QKV_E], g_vl[QKV_E];
__device__ __nv_bfloat16 g_oh[M_TOTAL * D_MODEL], g_ol[M_TOTAL * D_MODEL];

// ===========================================================================
// helpers
// ===========================================================================
static __device__ __forceinline__ uint32_t smem_u32(const void* p) {
    uint32_t a;
    asm("{ .reg .u64 t; cvta.to.shared.u64 t, %1; cvt.u32.u64 %0, t; }"
        : "=r"(a) : "l"(p));
    return a;
}

static __device__ __forceinline__ void ldsm_x4(uint32_t (&r)[4], uint32_t addr) {
    asm volatile("ldmatrix.sync.aligned.m8n8.x4.shared.b16 {%0,%1,%2,%3}, [%4];"
                 : "=r"(r[0]), "=r"(r[1]), "=r"(r[2]), "=r"(r[3]) : "r"(addr));
}

static __device__ __forceinline__ void ldsm_x4_t(uint32_t (&r)[4], uint32_t addr) {
    asm volatile("ldmatrix.sync.aligned.m8n8.x4.trans.shared.b16 {%0,%1,%2,%3}, [%4];"
                 : "=r"(r[0]), "=r"(r[1]), "=r"(r[2]), "=r"(r[3]) : "r"(addr));
}

static __device__ __forceinline__ void mma16816(float (&d)[4],
                                                const uint32_t (&a)[4],
                                                const uint32_t* b)
{
    asm volatile(
        "mma.sync.aligned.m16n8k16.row.col.f32.bf16.bf16.f32 "
        "{%0,%1,%2,%3}, {%4,%5,%6,%7}, {%8,%9}, {%0,%1,%2,%3};"
        : "+f"(d[0]), "+f"(d[1]), "+f"(d[2]), "+f"(d[3])
        : "r"(a[0]), "r"(a[1]), "r"(a[2]), "r"(a[3]), "r"(b[0]), "r"(b[1]));
}

#define CP16(dst, src) \
    asm volatile("cp.async.cg.shared.global [%0], [%1], 16;" \
                 :: "r"(dst), "l"(src) : "memory")
#define CP_COMMIT() asm volatile("cp.async.commit_group;" ::: "memory")
#define CP_WAIT0()  asm volatile("cp.async.wait_group 0;" ::: "memory")
#define CP_WAIT1()  asm volatile("cp.async.wait_group 1;" ::: "memory")

static __device__ __forceinline__ uint32_t pack_bf16x2(float a, float b) {
    __nv_bfloat162 t = __floats2bfloat162_rn(a, b);
    return *reinterpret_cast<uint32_t*>(&t);
}

static __device__ __forceinline__ void split2_store(__nv_bfloat16* H, __nv_bfloat16* L,
                                                    size_t idx, float v0, float v1)
{
    __nv_bfloat16 h0 = __float2bfloat16(v0), h1 = __float2bfloat16(v1);
    *(uint32_t*)(H + idx) = pack_bf16x2(v0, v1);
    *(uint32_t*)(L + idx) = pack_bf16x2(v0 - __bfloat162float(h0),
                                        v1 - __bfloat162float(h1));
}

// ===========================================================================
// split pass: fp32 -> hi/lo bf16
// ===========================================================================
__global__ __launch_bounds__(256)
void split_kernel(const float* __restrict__ src, __nv_bfloat16* __restrict__ H,
                  __nv_bfloat16* __restrict__ L, int n4)
{
    for (int i = blockIdx.x * blockDim.x + threadIdx.x; i < n4;
         i += gridDim.x * blockDim.x) {
        float4 v = __ldg((const float4*)src + i);
        split2_store(H, L, (size_t)i * 4 + 0, v.x, v.y);
        split2_store(H, L, (size_t)i * 4 + 2, v.z, v.w);
    }
}

// ===========================================================================
// GEMM: C = (Ah+Al) @ (Bh+Bl)^T + bias   (3-term bf16 split, HMMA)
// A: [M,1024] bf16 hi/lo. B(W): [1024,1024] row-major (N x K) hi/lo.
// CTA 128x128, BK=32, double-buffered cp.async staging.
// mode 0: fp32 out [M,1024].  mode 1: split QKV out [B,H,S,Dh], val*scale.
// ===========================================================================
#define STRIDE  40                        // padded smem row (bf16 elems), 80B
#define TILE_E  (128 * STRIDE)            // 5120 elems per tile
#define STAGE_E (4 * TILE_E)              // Ah,Al,Bh,Bl
#define GEMM_SMEM_B (2 * STAGE_E * 2)     // bytes = 81920

extern __shared__ __nv_bfloat16 dsm[];

static __device__ __forceinline__ void gemm_issue(const __nv_bfloat16* Ah,
                                                  const __nv_bfloat16* Al,
                                                  const __nv_bfloat16* Bh,
                                                  const __nv_bfloat16* Bl,
                                                  uint32_t sb, int stage,
                                                  int bm, int bn, int k0, int tid)
{
    const uint32_t base = sb + (uint32_t)(stage * STAGE_E) * 2;
    #pragma unroll
    for (int i = 0; i < 2; i++) {
        const int idx = tid + i * 256;          // 0..511
        const int row = idx >> 2, c = idx & 3;  // row 0..127, 16B chunk 0..3
        const size_t gofs = (size_t)row * D_MODEL + k0 + c * 8;
        const uint32_t sofs = (uint32_t)(row * STRIDE + c * 8) * 2;
        CP16(base + 0 * TILE_E * 2 + sofs, Ah + (size_t)bm * D_MODEL + gofs);
        CP16(base + 1 * TILE_E * 2 + sofs, Al + (size_t)bm * D_MODEL + gofs);
        CP16(base + 2 * TILE_E * 2 + sofs, Bh + (size_t)bn * D_MODEL + gofs);
        CP16(base + 3 * TILE_E * 2 + sofs, Bl + (size_t)bn * D_MODEL + gofs);
    }
}

static __device__ __forceinline__ void gemm_tc_body(const __nv_bfloat16* __restrict__ Ah,
                                                    const __nv_bfloat16* __restrict__ Al,
                                                    const __nv_bfloat16* __restrict__ Bh,
                                                    const __nv_bfloat16* __restrict__ Bl,
                                                    const float* __restrict__ bias,
                                                    float* __restrict__ Cf,
                                                    __nv_bfloat16* __restrict__ Ch,
                                                    __nv_bfloat16* __restrict__ Cl,
                                                    int mode, float scale)
{
    const uint32_t sb = smem_u32(dsm);
    const int tid  = threadIdx.x;
    const int wid  = tid >> 5;
    const int lane = tid & 31;
    const int bm = blockIdx.y * 128;
    const int bn = blockIdx.x * 128;
    const int warp_m = (wid & 1) * 64;
    const int warp_n = (wid >> 1) * 32;

    float acc[4][4][4];
    #pragma unroll
    for (int i = 0; i < 4; i++)
        #pragma unroll
        for (int j = 0; j < 4; j++)
            #pragma unroll
            for (int c = 0; c < 4; c++) acc[i][j][c] = 0.f;

    gemm_issue(Ah, Al, Bh, Bl, sb, 0, bm, bn, 0, tid);
    CP_COMMIT();

    #pragma unroll 1
    for (int chunk = 0; chunk < D_MODEL / 32; chunk++) {
        const int cur = chunk & 1;
        if (chunk + 1 < D_MODEL / 32) {
            gemm_issue(Ah, Al, Bh, Bl, sb, cur ^ 1, bm, bn, (chunk + 1) * 32, tid);
            CP_COMMIT();
            CP_WAIT1();
        } else {
            CP_WAIT0();
        }
        __syncthreads();

        const uint32_t uAh = sb + (uint32_t)(cur * STAGE_E + 0 * TILE_E) * 2;
        const uint32_t uAl = sb + (uint32_t)(cur * STAGE_E + 1 * TILE_E) * 2;
        const uint32_t uBh = sb + (uint32_t)(cur * STAGE_E + 2 * TILE_E) * 2;
        const uint32_t uBl = sb + (uint32_t)(cur * STAGE_E + 3 * TILE_E) * 2;

        #pragma unroll
        for (int ks = 0; ks < 2; ks++) {
            uint32_t ah[4][4], al[4][4];
            {
                const int row = ((lane >> 3) & 1) * 8 + (lane & 7);
                const int kk  = ks * 16 + ((lane >> 4) & 1) * 8;
                #pragma unroll
                for (int mf = 0; mf < 4; mf++) {
                    const uint32_t off =
                        (uint32_t)(((warp_m + mf * 16 + row) * STRIDE + kk) * 2);
                    ldsm_x4(ah[mf], uAh + off);
                    ldsm_x4(al[mf], uAl + off);
                }
            }
            uint32_t bh[2][4], bl[2][4];
            {
                const int row = ((lane >> 4) & 1) * 8 + (lane & 7);
                const int kk  = ks * 16 + ((lane >> 3) & 1) * 8;
                #pragma unroll
                for (int nb = 0; nb < 2; nb++) {
                    const uint32_t off =
                        (uint32_t)(((warp_n + nb * 16 + row) * STRIDE + kk) * 2);
                    ldsm_x4(bh[nb], uBh + off);
                    ldsm_x4(bl[nb], uBl + off);
                }
            }
            #pragma unroll
            for (int mf = 0; mf < 4; mf++)
                #pragma unroll
                for (int nf = 0; nf < 4; nf++) {
                    const int nb = nf >> 1, o = (nf & 1) * 2;
                    mma16816(acc[mf][nf], ah[mf], &bh[nb][o]);
                    mma16816(acc[mf][nf], ah[mf], &bl[nb][o]);
                    mma16816(acc[mf][nf], al[mf], &bh[nb][o]);
                }
        }
        __syncthreads();
    }

    const int er = lane >> 2;
    const int ec = (lane & 3) * 2;
    #pragma unroll
    for (int mf = 0; mf < 4; mf++) {
        #pragma unroll
        for (int nf = 0; nf < 4; nf++) {
            const int n = bn + warp_n + nf * 8 + ec;
            const float b0 = __ldg(bias + n), b1 = __ldg(bias + n + 1);
            #pragma unroll
            for (int half = 0; half < 2; half++) {
                const int m = bm + warp_m + mf * 16 + er + half * 8;
                const float v0 = (acc[mf][nf][half * 2 + 0] + b0) * scale;
                const float v1 = (acc[mf][nf][half * 2 + 1] + b1) * scale;
                if (mode == 0) {
                    float2 r; r.x = v0; r.y = v1;
                    *(float2*)(Cf + (size_t)m * D_MODEL + n) = r;
                } else {
                    const int bb = m >> 11, s = m & 2047;
                    const int h = n >> 6,  d = n & 63;
                    const size_t idx =
                        (((size_t)(bb * NUM_HEADS + h) * SEQ + s) << 6) + d;
                    split2_store(Ch, Cl, idx, v0, v1);
                }
            }
        }
    }
}

__global__ __launch_bounds__(256)
void qkv_gemm_kernel(const float* __restrict__ bq, const float* __restrict__ bk,
                     const float* __restrict__ bv)
{
    if (blockIdx.z == 0)
        gemm_tc_body(g_xh, g_xl, g_wqh, g_wql, bq, nullptr, g_qh, g_ql, 1, 0.125f);
    else if (blockIdx.z == 1)
        gemm_tc_body(g_xh, g_xl, g_wkh, g_wkl, bk, nullptr, g_kh, g_kl, 1, 1.0f);
    else
        gemm_tc_body(g_xh, g_xl, g_wvh, g_wvl, bv, nullptr, g_vh, g_vl, 1, 1.0f);
}

__global__ __launch_bounds__(256)
void out_gemm_kernel(const float* __restrict__ bo, float* __restrict__ out)
{
    gemm_tc_body(g_oh, g_ol, g_woh, g_wol, bo, out, nullptr, nullptr, 0, 1.0f);
}

// ===========================================================================
// Tensor-core flash attention, pre-split inputs, cp.async double-buffered.
// CTA: 64 q-rows, 4 warps. K/V tiles of 64 keys.
// ===========================================================================
#define AT_STRIDE 72                       // bf16 elems per row (144B, 16B mult)
#define AT_TILE   (64 * AT_STRIDE)         // 4608 elems
#define AT_STAGE  (4 * AT_TILE)            // Kh,Kl,Vh,Vl
#define ATTN_SMEM_B (2 * AT_STAGE * 2)     // 73728 bytes

static __device__ __forceinline__ void attn_issue(uint32_t sb, int stage,
                                                  size_t kvbase, int kt, int tid)
{
    const uint32_t base = sb + (uint32_t)(stage * AT_STAGE) * 2;
    const __nv_bfloat16* srcs[4] = { g_kh, g_kl, g_vh, g_vl };
    #pragma unroll
    for (int i = 0; i < 16; i++) {
        const int idx = tid + i * 128;             // 0..2047
        const int arr = idx >> 9;                  // 0..3
        const int j   = idx & 511;
        const int row = j >> 3, c = j & 7;
        const __nv_bfloat16* src =
            srcs[arr] + kvbase + (size_t)(kt * 64 + row) * HEAD_DIM + c * 8;
        const uint32_t dst =
            base + (uint32_t)(arr * AT_TILE + row * AT_STRIDE + c * 8) * 2;
        CP16(dst, src);
    }
}

__global__ __launch_bounds__(128)
void attn_kernel()
{
    const uint32_t sb = smem_u32(dsm);

    const int bh    = blockIdx.x;            // b*16 + h
    const int qbase = blockIdx.y * 64;
    const int tid   = threadIdx.x;
    const int wid   = tid >> 5;
    const int lane  = tid & 31;
    const int warp_m = wid * 16;

    const size_t kvbase = (size_t)bh * SEQ * HEAD_DIM;

    // ---- stage Q (already scaled+split) into stage-0 Kh/Kl area
    #pragma unroll
    for (int i = 0; i < 8; i++) {
        const int idx = tid + i * 128;           // 0..1023
        const int arr = idx >> 9;                // 0: hi, 1: lo
        const int j   = idx & 511;
        const int row = j >> 3, c = j & 7;
        const __nv_bfloat16* src =
            (arr == 0 ? g_qh : g_ql) + kvbase + (size_t)(qbase + row) * HEAD_DIM + c * 8;
        const uint32_t dst = sb + (uint32_t)(arr * AT_TILE + row * AT_STRIDE + c * 8) * 2;
        CP16(dst, src);
    }
    CP_COMMIT();
    CP_WAIT0();
    __syncthreads();

    uint32_t qh[4][4], ql[4][4];
    {
        const int row = warp_m + ((lane >> 3) & 1) * 8 + (lane & 7);
        #pragma unroll
        for (int ks = 0; ks < 4; ks++) {
            const int kk = ks * 16 + ((lane >> 4) & 1) * 8;
            const uint32_t off = (uint32_t)((row * AT_STRIDE + kk) * 2);
            ldsm_x4(qh[ks], sb + off);
            ldsm_x4(ql[ks], sb + (uint32_t)(AT_TILE * 2) + off);
        }
    }
    __syncthreads();

    float o[8][4];
    #pragma unroll
    for (int nf = 0; nf < 8; nf++)
        #pragma unroll
        for (int c = 0; c < 4; c++) o[nf][c] = 0.f;
    float m0 = -1e30f, m1 = -1e30f, l0 = 0.f, l1 = 0.f;

    attn_issue(sb, 0, kvbase, 0, tid);
    CP_COMMIT();

    #pragma unroll 1
    for (int kt = 0; kt < SEQ / 64; kt++) {
        const int cur = kt & 1;
        if (kt + 1 < SEQ / 64) {
            attn_issue(sb, cur ^ 1, kvbase, kt + 1, tid);
            CP_COMMIT();
            CP_WAIT1();
        } else {
            CP_WAIT0();
        }
        __syncthreads();

        const uint32_t uKh = sb + (uint32_t)(cur * AT_STAGE + 0 * AT_TILE) * 2;
        const uint32_t uKl = sb + (uint32_t)(cur * AT_STAGE + 1 * AT_TILE) * 2;
        const uint32_t uVh = sb + (uint32_t)(cur * AT_STAGE + 2 * AT_TILE) * 2;
        const uint32_t uVl = sb + (uint32_t)(cur * AT_STAGE + 3 * AT_TILE) * 2;

        // ---- S = Q K^T
        float s[8][4];
        #pragma unroll
        for (int nf = 0; nf < 8; nf++)
            #pragma unroll
            for (int c = 0; c < 4; c++) s[nf][c] = 0.f;

        #pragma unroll
        for (int ks = 0; ks < 4; ks++) {
            uint32_t kbh[4][4], kbl[4][4];
            const int row = ((lane >> 4) & 1) * 8 + (lane & 7);
            const int kk  = ks * 16 + ((lane >> 3) & 1) * 8;
            #pragma unroll
            for (int nb = 0; nb < 4; nb++) {
                const uint32_t off =
                    (uint32_t)(((nb * 16 + row) * AT_STRIDE + kk) * 2);
                ldsm_x4(kbh[nb], uKh + off);
                ldsm_x4(kbl[nb], uKl + off);
            }
            #pragma unroll
            for (int nf = 0; nf < 8; nf++) {
                const int nb = nf >> 1, oo = (nf & 1) * 2;
                mma16816(s[nf], qh[ks], &kbh[nb][oo]);
                mma16816(s[nf], qh[ks], &kbl[nb][oo]);
                mma16816(s[nf], ql[ks], &kbh[nb][oo]);
            }
        }

        // ---- online softmax
        float mn0 = m0, mn1 = m1;
        #pragma unroll
        for (int nf = 0; nf < 8; nf++) {
            mn0 = fmaxf(mn0, fmaxf(s[nf][0], s[nf][1]));
            mn1 = fmaxf(mn1, fmaxf(s[nf][2], s[nf][3]));
        }
        mn0 = fmaxf(mn0, __shfl_xor_sync(0xffffffffu, mn0, 1));
        mn0 = fmaxf(mn0, __shfl_xor_sync(0xffffffffu, mn0, 2));
        mn1 = fmaxf(mn1, __shfl_xor_sync(0xffffffffu, mn1, 1));
        mn1 = fmaxf(mn1, __shfl_xor_sync(0xffffffffu, mn1, 2));
        const float c0 = __expf(m0 - mn0);
        const float c1 = __expf(m1 - mn1);
        m0 = mn0; m1 = mn1;
        l0 *= c0;  l1 *= c1;
        #pragma unroll
        for (int nf = 0; nf < 8; nf++) {
            o[nf][0] *= c0; o[nf][1] *= c0;
            o[nf][2] *= c1; o[nf][3] *= c1;
        }

        // ---- P = exp(S - m), split into A-fragments
        uint32_t pah[4][4], pal[4][4];
        #pragma unroll
        for (int nf = 0; nf < 8; nf++) {
            const float p0 = __expf(s[nf][0] - m0);
            const float p1 = __expf(s[nf][1] - m0);
            const float p2 = __expf(s[nf][2] - m1);
            const float p3 = __expf(s[nf][3] - m1);
            l0 += p0 + p1;
            l1 += p2 + p3;
            __nv_bfloat16 h0 = __float2bfloat16(p0), h1 = __float2bfloat16(p1);
            __nv_bfloat16 h2 = __float2bfloat16(p2), h3 = __float2bfloat16(p3);
            const int ks = nf >> 1, base = (nf & 1) * 2;
            pah[ks][base + 0] = pack_bf16x2(p0, p1);
            pah[ks][base + 1] = pack_bf16x2(p2, p3);
            pal[ks][base + 0] = pack_bf16x2(p0 - __bfloat162float(h0),
                                            p1 - __bfloat162float(h1));
            pal[ks][base + 1] = pack_bf16x2(p2 - __bfloat162float(h2),
                                            p3 - __bfloat162float(h3));
        }

        // ---- O += P V
        #pragma unroll
        for (int ks = 0; ks < 4; ks++) {
            const int krow = ks * 16 + ((lane >> 3) & 1) * 8 + (lane & 7);
            #pragma unroll
            for (int half = 0; half < 2; half++) {
                uint32_t vbh[2][4], vbl[2][4];
                #pragma unroll
                for (int nb = 0; nb < 2; nb++) {
                    const int dh = half * 32 + nb * 16 + ((lane >> 4) & 1) * 8;
                    const uint32_t off = (uint32_t)((krow * AT_STRIDE + dh) * 2);
                    ldsm_x4_t(vbh[nb], uVh + off);
                    ldsm_x4_t(vbl[nb], uVl + off);
                }
                #pragma unroll
                for (int nf = 0; nf < 4; nf++) {
                    const int nb = nf >> 1, oo = (nf & 1) * 2;
                    mma16816(o[half * 4 + nf], pah[ks], &vbh[nb][oo]);
                    mma16816(o[half * 4 + nf], pah[ks], &vbl[nb][oo]);
                    mma16816(o[half * 4 + nf], pal[ks], &vbh[nb][oo]);
                }
            }
        }
        __syncthreads();
    }

    // ---- finalize
    l0 += __shfl_xor_sync(0xffffffffu, l0, 1);
    l0 += __shfl_xor_sync(0xffffffffu, l0, 2);
    l1 += __shfl_xor_sync(0xffffffffu, l1, 1);
    l1 += __shfl_xor_sync(0xffffffffu, l1, 2);
    const float inv0 = 1.0f / l0, inv1 = 1.0f / l1;

    const int b = bh >> 4, h = bh & 15;
    const int row0 = qbase + warp_m + (lane >> 2);
    const int ec = (lane & 3) * 2;
    #pragma unroll
    for (int nf = 0; nf < 8; nf++) {
        const int dh = nf * 8 + ec;
        split2_store(g_oh, g_ol,
                     (size_t)(b * SEQ + row0) * D_MODEL + h * 64 + dh,
                     o[nf][0] * inv0, o[nf][1] * inv0);
        split2_store(g_oh, g_ol,
                     (size_t)(b * SEQ + row0 + 8) * D_MODEL + h * 64 + dh,
                     o[nf][2] * inv1, o[nf][3] * inv1);
    }
}

// ---------------------------------------------------------------------------
extern "C" void kernel_launch(void* const* d_in, const int* in_sizes, int n_in,
                              void* d_out, int out_size)
{
    const float* x  = (const float*)d_in[0];
    const float* Wq = (const float*)d_in[1];
    const float* bq = (const float*)d_in[2];
    const float* Wk = (const float*)d_in[3];
    const float* bk = (const float*)d_in[4];
    const float* Wv = (const float*)d_in[5];
    const float* bv = (const float*)d_in[6];
    const float* Wo = (const float*)d_in[7];
    const float* bo = (const float*)d_in[8];
    float* out = (float*)d_out;

    static int attr_done = 0;
    if (!attr_done) {
        cudaFuncSetAttribute(qkv_gemm_kernel,
                             cudaFuncAttributeMaxDynamicSharedMemorySize, GEMM_SMEM_B);
        cudaFuncSetAttribute(out_gemm_kernel,
                             cudaFuncAttributeMaxDynamicSharedMemorySize, GEMM_SMEM_B);
        cudaFuncSetAttribute(attn_kernel,
                             cudaFuncAttributeMaxDynamicSharedMemorySize, ATTN_SMEM_B);
        attr_done = 1;
    }

    // device-global pointers (host side)
    __nv_bfloat16 *xh, *xl, *wqh, *wql, *wkh, *wkl, *wvh, *wvl, *woh, *wol;
    cudaGetSymbolAddress((void**)&xh,  g_xh);  cudaGetSymbolAddress((void**)&xl,  g_xl);
    cudaGetSymbolAddress((void**)&wqh, g_wqh); cudaGetSymbolAddress((void**)&wql, g_wql);
    cudaGetSymbolAddress((void**)&wkh, g_wkh); cudaGetSymbolAddress((void**)&wkl, g_wkl);
    cudaGetSymbolAddress((void**)&wvh, g_wvh); cudaGetSymbolAddress((void**)&wvl, g_wvl);
    cudaGetSymbolAddress((void**)&woh, g_woh); cudaGetSymbolAddress((void**)&wol, g_wol);

    // split passes
    split_kernel<<<1024, 256>>>(x,  xh,  xl,  M_TOTAL * D_MODEL / 4);
    split_kernel<<<256,  256>>>(Wq, wqh, wql, D_MODEL * D_MODEL / 4);
    split_kernel<<<256,  256>>>(Wk, wkh, wkl, D_MODEL * D_MODEL / 4);
    split_kernel<<<256,  256>>>(Wv, wvh, wvl, D_MODEL * D_MODEL / 4);
    split_kernel<<<256,  256>>>(Wo, woh, wol, D_MODEL * D_MODEL / 4);

    // QKV projections
    dim3 gqkv(D_MODEL / 128, M_TOTAL / 128, 3);
    qkv_gemm_kernel<<<gqkv, 256, GEMM_SMEM_B>>>(bq, bk, bv);

    // Attention
    dim3 gattn(BATCH * NUM_HEADS, SEQ / 64);
    attn_kernel<<<gattn, 128, ATTN_SMEM_B>>>();

    // Output projection
    dim3 gout(D_MODEL / 128, M_TOTAL / 128);
    out_gemm_kernel<<<gout, 256, GEMM_SMEM_B>>>(bo, out);
}